// round 6
// baseline (speedup 1.0000x reference)
// LinearNO on GB300 — round 5: split-K f32x2 phase A (no dup movs), pre-dup'd
// smem weights for phase B / K6, MLP-fixed K5.
//  K0 : AqkT[64][512] = (W_in @ blockdiag(W_q|W_k))^T ; c_qk
//  K1f: per 256-row chunk (512 thr, 1 CTA/SM):
//       A: logits = x@Aqk+c (split-K pairs) ; qsm ; chunk k-stats
//       B: Spart[b][ch][j][512] (n split across thread halves + smem reduce)
//  K2b: scale[b][ch][j]
//  K5 : U = ((S @ W_in_h + b_in_h) @ W_v) @ W_out_h  (MLP-8 reduction)
//  K6 : out = b_out + qsm @ U
#include <cuda_runtime.h>
#include <cstdint>

typedef unsigned long long ull;

#define Bb   8
#define Nn   16384
#define DIMM 512
#define Hh   8
#define DHh  64
#define Rr   4
#define Jj   32
#define SCH  64          // chunks per batch (256 rows each)

// ---------------- scratch ----------------
__device__ __align__(16) float g_AqkT[64 * DIMM];               // [c][D]
__device__ __align__(16) float g_cqk[64];
__device__ __align__(16) float g_qsm[(size_t)Bb * Nn * Jj];     // [b][n][32]
__device__ __align__(16) float g_mloc[(size_t)Bb * SCH * Jj];
__device__ __align__(16) float g_zloc[(size_t)Bb * SCH * Jj];
__device__ __align__(16) float g_scale[(size_t)Bb * SCH * Jj];
__device__ __align__(16) float g_Spart[(size_t)Bb * SCH * Jj * DIMM];
__device__ __align__(16) float g_U[(size_t)Bb * Jj * DIMM];

// ---------------- helpers ----------------
__device__ __forceinline__ ull ffma2(ull a, ull b, ull c) {
    ull d;
    asm("fma.rn.f32x2 %0, %1, %2, %3;" : "=l"(d) : "l"(a), "l"(b), "l"(c));
    return d;
}
__device__ __forceinline__ ull add2(ull a, ull b) {
    ull d;
    asm("add.rn.f32x2 %0, %1, %2;" : "=l"(d) : "l"(a), "l"(b));
    return d;
}
__device__ __forceinline__ ull dup2(float f) {
    unsigned u = __float_as_uint(f);
    ull d;
    asm("mov.b64 %0, {%1, %1};" : "=l"(d) : "r"(u));
    return d;
}
__device__ __forceinline__ float ulo(ull u) { return __uint_as_float((unsigned)u); }
__device__ __forceinline__ float uhi(ull u) { return __uint_as_float((unsigned)(u >> 32)); }

__device__ __forceinline__ void cpa16(uint32_t smem_dst, const void* gsrc) {
    asm volatile("cp.async.cg.shared.global [%0], [%1], 16;" :: "r"(smem_dst), "l"(gsrc));
}
__device__ __forceinline__ void cpa_commit() { asm volatile("cp.async.commit_group;"); }
__device__ __forceinline__ void cpa_wait1() { asm volatile("cp.async.wait_group 1;"); }
__device__ __forceinline__ void cpa_wait0() { asm volatile("cp.async.wait_group 0;"); }

// ---------------- K0 ----------------
__global__ void k0_prep(const float* __restrict__ W_in, const float* __restrict__ b_in,
                        const float* __restrict__ W_q, const float* __restrict__ W_k) {
    int j = blockIdx.x;                      // 0..63 (q: 0..31, k: 32..63)
    const float* Wqk = (j < 32) ? W_q : W_k;
    int jj = j & 31, h = jj >> 2, r = jj & 3;
    int D = threadIdx.x;                     // 512 threads
    const float* wrow = W_in + (size_t)D * DIMM + h * DHh;
    float s = 0.f;
    #pragma unroll 8
    for (int d = 0; d < DHh; d++) s += wrow[d] * Wqk[d * Rr + r];
    g_AqkT[(size_t)j * DIMM + D] = s;
    if (D == 0) {
        float c = 0.f;
        for (int d = 0; d < DHh; d++) c += b_in[h * DHh + d] * Wqk[d * Rr + r];
        g_cqk[j] = c;
    }
}

// ---------------- K1f ----------------
// smem (dynamic, 133376 B):
//  phase A : xs  [0, 73728)       2*256*36 f32
//            wT  [73728, 92160)   2*64*36 f32
//  epilogue: stag[0, 65792)       64*257 f32  (reuses xs)
//            wsmd[65792, 131328)  256*32 ull
//            mred[131328,132352) zred[132352,133376)
//  phase B : xs2 [0, 32768)       2*8*512 f32 ; red2 = xs2 region at the end
#define K1F_SMEM 133376

__global__ void __launch_bounds__(512, 1) k1f(const float* __restrict__ x) {
    extern __shared__ char sm[];
    float* xs = (float*)sm;
    float* wT = (float*)(sm + 73728);
    int tid = threadIdx.x;
    int bi  = blockIdx.x;                  // 0..511
    size_t row0 = (size_t)bi * 256;
    int b  = (int)(row0 >> 14);
    int n0 = (int)(row0 & (Nn - 1));
    const float* xb = x + row0 * DIMM;
    uint32_t xs_s = (uint32_t)__cvta_generic_to_shared(xs);
    uint32_t wT_s = (uint32_t)__cvta_generic_to_shared(wT);

    // ================= Phase A: logits (split-K pairs) =================
    int cg = tid & 15, rg = tid >> 4;      // cols cg+16j, rows rg*8..+7
    int r0 = rg * 8;

    ull acc[8][4];
    #pragma unroll
    for (int i = 0; i < 8; i++)
        #pragma unroll
        for (int j = 0; j < 4; j++) acc[i][j] = 0ull;

    #define K1_ISSUE(s) do {                                                     \
        int buf_ = (s) & 1;                                                      \
        _Pragma("unroll")                                                        \
        for (int i_ = 0; i_ < 4; i_++) {                                         \
            int idx_ = tid + i_ * 512;         /* 2048 cpa16: x 256x32 */        \
            int row_ = idx_ >> 3, seg_ = idx_ & 7;                               \
            cpa16(xs_s + (uint32_t)(buf_ * 36864 + row_ * 144 + seg_ * 16),      \
                  xb + (size_t)row_ * DIMM + (s) * 32 + seg_ * 4);               \
        }                                                                        \
        { int c_ = tid >> 3, seg_ = tid & 7;   /* 512 cpa16: w 64x32 */          \
          cpa16(wT_s + (uint32_t)(buf_ * 9216 + c_ * 144 + seg_ * 16),           \
                g_AqkT + (size_t)c_ * DIMM + (s) * 32 + seg_ * 4); }             \
    } while (0)

    K1_ISSUE(0); cpa_commit();
    for (int s = 0; s < 16; s++) {
        if (s < 15) { K1_ISSUE(s + 1); cpa_commit(); cpa_wait1(); }
        else        { cpa_wait0(); }
        __syncthreads();
        const float* xbuf = xs + (s & 1) * 9216;
        const float* wbuf = wT + (s & 1) * 2304;
        #pragma unroll
        for (int k0 = 0; k0 < 32; k0 += 4) {
            ulonglong2 wv[4];
            #pragma unroll
            for (int j = 0; j < 4; j++)
                wv[j] = *(const ulonglong2*)(wbuf + (cg + 16 * j) * 36 + k0);
            #pragma unroll
            for (int i = 0; i < 8; i++) {
                ulonglong2 xv = *(const ulonglong2*)(xbuf + (r0 + i) * 36 + k0);
                #pragma unroll
                for (int j = 0; j < 4; j++) acc[i][j] = ffma2(xv.x, wv[j].x, acc[i][j]);
                #pragma unroll
                for (int j = 0; j < 4; j++) acc[i][j] = ffma2(xv.y, wv[j].y, acc[i][j]);
            }
        }
        __syncthreads();
    }

    // ================= Epilogue =================
    float* stag = (float*)sm;                  // [64 c][257]
    ull*   wsmd = (ull*)(sm + 65792);          // [256 n][32 j] pre-dup'd
    float* mred = (float*)(sm + 131328);
    float* zred = (float*)(sm + 132352);

    {
        float cq[4];
        #pragma unroll
        for (int j = 0; j < 4; j++) cq[j] = g_cqk[cg + 16 * j];
        #pragma unroll
        for (int i = 0; i < 8; i++)
            #pragma unroll
            for (int j = 0; j < 4; j++)
                stag[(cg + 16 * j) * 257 + r0 + i] = ulo(acc[i][j]) + uhi(acc[i][j]) + cq[j];
    }
    __syncthreads();

    // q softmax (threads 0..255, one n each)
    if (tid < 256) {
        float4 qs[8];
        #pragma unroll
        for (int h = 0; h < 8; h++) {
            float v0 = stag[(4 * h + 0) * 257 + tid];
            float v1 = stag[(4 * h + 1) * 257 + tid];
            float v2 = stag[(4 * h + 2) * 257 + tid];
            float v3 = stag[(4 * h + 3) * 257 + tid];
            float mx = fmaxf(fmaxf(v0, v1), fmaxf(v2, v3));
            float e0 = __expf(v0 - mx), e1 = __expf(v1 - mx);
            float e2 = __expf(v2 - mx), e3 = __expf(v3 - mx);
            float inv = 1.0f / (e0 + e1 + e2 + e3);
            qs[h] = make_float4(e0 * inv, e1 * inv, e2 * inv, e3 * inv);
        }
        float* dst = g_qsm + ((size_t)b * Nn + n0 + tid) * Jj;
        #pragma unroll
        for (int h = 0; h < 8; h++) *(float4*)(dst + h * 4) = qs[h];
    }

    // k chunk stats (threads 0..255: j = tid&31, grp = tid>>5)
    int jS = tid & 31, grp = tid >> 5;
    const float* kl = stag + (32 + jS) * 257 + (grp & 7) * 32;
    if (grp < 8) {
        float mloc = -3.4e38f;
        #pragma unroll 8
        for (int nn = 0; nn < 32; nn++) mloc = fmaxf(mloc, kl[nn]);
        mred[grp * 32 + jS] = mloc;
    }
    __syncthreads();
    if (grp < 8) {
        float Mj = -3.4e38f;
        #pragma unroll
        for (int g = 0; g < 8; g++) Mj = fmaxf(Mj, mred[g * 32 + jS]);
        float zloc = 0.f;
        #pragma unroll 8
        for (int nn = 0; nn < 32; nn++) {
            float w = __expf(kl[nn] - Mj);
            zloc += w;
            wsmd[(grp * 32 + nn) * 32 + jS] = dup2(w);
        }
        zred[grp * 32 + jS] = zloc;
        if (grp == 0) g_mloc[(size_t)bi * Jj + jS] = Mj;
    }
    __syncthreads();
    if (tid < 32) {
        float z = 0.f;
        #pragma unroll
        for (int g = 0; g < 8; g++) z += zred[g * 32 + tid];
        g_zloc[(size_t)bi * Jj + tid] = z;
    }

    // ================= Phase B: S partials (n split across halves) =================
    float* xs2 = (float*)sm;                   // [0,32768): clear of stag rows 32..63
    uint32_t xs2_s = xs_s;
    int hf = tid >> 8;                         // 0/1 : n-half
    int t  = tid & 255;
    int jg = t >> 6, j0 = jg * 8;
    int dg = t & 63, d0 = dg * 4;

    #define K3_ISSUE(s) do {                                                     \
        int buf_ = (s) & 1;                                                      \
        _Pragma("unroll")                                                        \
        for (int t_ = 0; t_ < 2; t_++) {                                         \
            int c_ = tid + t_ * 512;                                             \
            cpa16(xs2_s + (uint32_t)(buf_ * 16384 + c_ * 16),                    \
                  xb + (size_t)(s) * 4096 + c_ * 4);                             \
        }                                                                        \
    } while (0)

    ull sacc[8][4];
    #pragma unroll
    for (int i = 0; i < 8; i++)
        #pragma unroll
        for (int m = 0; m < 4; m++) sacc[i][m] = 0ull;

    K3_ISSUE(0); cpa_commit();
    for (int s = 0; s < 32; s++) {
        if (s < 31) { K3_ISSUE(s + 1); cpa_commit(); cpa_wait1(); }
        else        { cpa_wait0(); }
        __syncthreads();
        const float* xbuf = xs2 + (s & 1) * 4096;
        const ull*   wrow = wsmd + (size_t)s * 8 * 32;
        #pragma unroll
        for (int nn = 0; nn < 4; nn++) {
            int nloc = hf * 4 + nn;
            ull wd[8];
            #pragma unroll
            for (int i = 0; i < 8; i++) wd[i] = wrow[nloc * 32 + j0 + i];
            const float* xr = xbuf + nloc * 512;
            ulonglong2 x01 = *(const ulonglong2*)(xr + d0);
            ulonglong2 x23 = *(const ulonglong2*)(xr + 256 + d0);
            #pragma unroll
            for (int i = 0; i < 8; i++) {
                sacc[i][0] = ffma2(wd[i], x01.x, sacc[i][0]);
                sacc[i][1] = ffma2(wd[i], x01.y, sacc[i][1]);
                sacc[i][2] = ffma2(wd[i], x23.x, sacc[i][2]);
                sacc[i][3] = ffma2(wd[i], x23.y, sacc[i][3]);
            }
        }
        __syncthreads();
    }

    // cross-half reduction via smem (two 32 KB waves)
    ull* red2 = (ull*)sm;
    #pragma unroll
    for (int wave = 0; wave < 2; wave++) {
        if (hf == 1 && (t >> 7) == wave) {
            ull* p = red2 + (size_t)(t & 127) * 32;
            #pragma unroll
            for (int i = 0; i < 8; i++)
                #pragma unroll
                for (int m = 0; m < 4; m++) p[i * 4 + m] = sacc[i][m];
        }
        __syncthreads();
        if (hf == 0 && (t >> 7) == wave) {
            const ull* p = red2 + (size_t)(t & 127) * 32;
            #pragma unroll
            for (int i = 0; i < 8; i++)
                #pragma unroll
                for (int m = 0; m < 4; m++) sacc[i][m] = add2(sacc[i][m], p[i * 4 + m]);
        }
        __syncthreads();
    }

    if (hf == 0) {
        float* dst = g_Spart + ((size_t)bi * Jj) * DIMM;
        #pragma unroll
        for (int i = 0; i < 8; i++) {
            int j = j0 + i;
            *(float4*)(dst + (size_t)j * DIMM + d0) =
                make_float4(ulo(sacc[i][0]), uhi(sacc[i][0]), ulo(sacc[i][1]), uhi(sacc[i][1]));
            *(float4*)(dst + (size_t)j * DIMM + 256 + d0) =
                make_float4(ulo(sacc[i][2]), uhi(sacc[i][2]), ulo(sacc[i][3]), uhi(sacc[i][3]));
        }
    }
}

// ---------------- K2b ----------------
__global__ void k2b_scale() {
    int bj = blockIdx.x;              // 0..255
    int b = bj >> 5, j = bj & 31;
    __shared__ float smv[64], szv[64];
    int ch = threadIdx.x;             // 64 threads
    float m = g_mloc[(size_t)(b * SCH + ch) * Jj + j];
    float z = g_zloc[(size_t)(b * SCH + ch) * Jj + j];
    smv[ch] = m;
    __syncthreads();
    float M = -3.4e38f;
    #pragma unroll
    for (int c = 0; c < 64; c++) M = fmaxf(M, smv[c]);
    szv[ch] = z * __expf(m - M);
    __syncthreads();
    float Z = 0.f;
    #pragma unroll
    for (int c = 0; c < 64; c++) Z += szv[c];
    g_scale[(size_t)(b * SCH + ch) * Jj + j] = __expf(m - M) / Z;
}

// ---------------- K5 ----------------
__global__ void __launch_bounds__(512) k5_U(
        const float* __restrict__ W_in, const float* __restrict__ b_in,
        const float* __restrict__ W_v, const float* __restrict__ W_out) {
    int bj = blockIdx.x;
    int b = bj >> 5, j = bj & 31, h = j >> 2;
    __shared__ float scl[SCH];
    __shared__ float Srow[DIMM];
    __shared__ float Tp[DIMM];
    __shared__ float T[DHh];
    __shared__ float kv[DHh];
    int tid = threadIdx.x;   // 512
    if (tid < SCH) scl[tid] = g_scale[(size_t)(b * SCH + tid) * Jj + j];
    __syncthreads();
    {
        const float* base = g_Spart + (((size_t)b * SCH) * Jj + j) * DIMM + tid;
        float a[8];
        #pragma unroll
        for (int u = 0; u < 8; u++) a[u] = 0.f;
        #pragma unroll
        for (int c8 = 0; c8 < 8; c8++)
            #pragma unroll
            for (int u = 0; u < 8; u++) {
                int ch = c8 * 8 + u;
                a[u] += base[(size_t)ch * (Jj * DIMM)] * scl[ch];
            }
        Srow[tid] = ((a[0] + a[1]) + (a[2] + a[3])) + ((a[4] + a[5]) + (a[6] + a[7]));
    }
    __syncthreads();
    {   // T[d] = b_in + sum_D Srow[D] * W_in[D][h*64+d], parallel over (d, Dpart)
        int d = tid & 63, part = tid >> 6;    // 8 parts of 64 D
        float s = 0.f;
        const float* wp = W_in + (size_t)(part * 64) * DIMM + h * DHh + d;
        #pragma unroll 8
        for (int Dp = 0; Dp < 64; Dp++) s += Srow[part * 64 + Dp] * wp[(size_t)Dp * DIMM];
        Tp[part * 64 + d] = s;
    }
    __syncthreads();
    if (tid < DHh) {
        float t = b_in[h * DHh + tid];
        #pragma unroll
        for (int p = 0; p < 8; p++) t += Tp[p * 64 + tid];
        T[tid] = t;
    }
    __syncthreads();
    if (tid < DHh) {
        float s = 0.f;
        for (int d = 0; d < DHh; d++) s += T[d] * W_v[d * DHh + tid];
        kv[tid] = s;
    }
    __syncthreads();
    {
        float u = 0.f;
        for (int c = 0; c < DHh; c++) u += kv[c] * W_out[(size_t)(h * DHh + c) * DIMM + tid];
        g_U[(size_t)bj * DIMM + tid] = u;
    }
}

// ---------------- K6: out = b_out + qsm @ U  (64n x 256e per block) ----------------
__global__ void __launch_bounds__(256) k6_out(const float* __restrict__ b_out,
                                              float* __restrict__ out) {
    __shared__ ull   qsd[64 * 33];     // [n][j] pre-dup'd
    __shared__ float us[Jj * 256];     // [j][e]
    __shared__ float bo[256];
    int tid = threadIdx.x;
    int b = blockIdx.z;
    int n0 = blockIdx.y * 64;
    int e0 = blockIdx.x * 256;

    #pragma unroll
    for (int t = 0; t < 2; t++) {
        int idx = tid + t * 256;       // 512 float4
        int row = idx >> 3, q = idx & 7;
        float4 v = *(const float4*)(g_qsm + ((size_t)b * Nn + n0 + row) * Jj + q * 4);
        ull* dq = qsd + row * 33 + q * 4;
        dq[0] = dup2(v.x); dq[1] = dup2(v.y); dq[2] = dup2(v.z); dq[3] = dup2(v.w);
    }
    #pragma unroll
    for (int t = 0; t < 8; t++) {
        int idx = tid + t * 256;       // 2048 float4
        int j = idx >> 6, q = idx & 63;
        ((float4*)us)[j * 64 + q] =
            *(const float4*)(g_U + ((size_t)(b * Jj + j)) * DIMM + e0 + q * 4);
    }
    if (tid < 64) ((float4*)bo)[tid] = *(const float4*)(b_out + e0 + tid * 4);
    __syncthreads();

    int tx = tid & 15, ty = tid >> 4;
    int nl = ty * 4, eb = tx * 4;
    ull acc[4][8];
    #pragma unroll
    for (int i = 0; i < 4; i++)
        #pragma unroll
        for (int m = 0; m < 8; m++) acc[i][m] = 0ull;

    #pragma unroll 4
    for (int j = 0; j < Jj; j++) {
        ull a[4];
        #pragma unroll
        for (int i = 0; i < 4; i++) a[i] = qsd[(nl + i) * 33 + j];
        const float* ur = us + j * 256;
        ulonglong2 u0 = *(const ulonglong2*)(ur + eb);
        ulonglong2 u1 = *(const ulonglong2*)(ur + 64 + eb);
        ulonglong2 u2 = *(const ulonglong2*)(ur + 128 + eb);
        ulonglong2 u3 = *(const ulonglong2*)(ur + 192 + eb);
        #pragma unroll
        for (int i = 0; i < 4; i++) {
            acc[i][0] = ffma2(a[i], u0.x, acc[i][0]);
            acc[i][1] = ffma2(a[i], u0.y, acc[i][1]);
            acc[i][2] = ffma2(a[i], u1.x, acc[i][2]);
            acc[i][3] = ffma2(a[i], u1.y, acc[i][3]);
            acc[i][4] = ffma2(a[i], u2.x, acc[i][4]);
            acc[i][5] = ffma2(a[i], u2.y, acc[i][5]);
            acc[i][6] = ffma2(a[i], u3.x, acc[i][6]);
            acc[i][7] = ffma2(a[i], u3.y, acc[i][7]);
        }
    }

    #pragma unroll
    for (int i = 0; i < 4; i++) {
        float* row = out + ((size_t)b * Nn + n0 + nl + i) * DIMM + e0;
        #pragma unroll
        for (int seg = 0; seg < 4; seg++) {
            float4 v;
            v.x = ulo(acc[i][2 * seg])     + bo[seg * 64 + eb + 0];
            v.y = uhi(acc[i][2 * seg])     + bo[seg * 64 + eb + 1];
            v.z = ulo(acc[i][2 * seg + 1]) + bo[seg * 64 + eb + 2];
            v.w = uhi(acc[i][2 * seg + 1]) + bo[seg * 64 + eb + 3];
            *(float4*)(row + seg * 64 + eb) = v;
        }
    }
}

// ---------------- launch ----------------
extern "C" void kernel_launch(void* const* d_in, const int* in_sizes, int n_in,
                              void* d_out, int out_size) {
    const float* x     = (const float*)d_in[0];
    const float* W_in  = (const float*)d_in[1];
    const float* b_in  = (const float*)d_in[2];
    const float* W_q   = (const float*)d_in[3];
    const float* W_k   = (const float*)d_in[4];
    const float* W_v   = (const float*)d_in[5];
    const float* W_out = (const float*)d_in[6];
    const float* b_out = (const float*)d_in[7];
    float* out = (float*)d_out;

    cudaFuncSetAttribute(k1f, cudaFuncAttributeMaxDynamicSharedMemorySize, K1F_SMEM);

    k0_prep<<<64, 512>>>(W_in, b_in, W_q, W_k);
    k1f<<<Bb * SCH, 512, K1F_SMEM>>>(x);
    k2b_scale<<<Bb * Jj, 64>>>();
    k5_U<<<Bb * Jj, 512>>>(W_in, b_in, W_v, W_out);
    dim3 g6(DIMM / 256, Nn / 64, Bb);
    k6_out<<<g6, 256>>>(b_out, out);
}

// round 8
// speedup vs baseline: 1.1256x; 1.1256x over previous
// LinearNO on GB300 — round 6: revert k1f to r4 (2 CTA/SM, proven 506.7),
// keep r5's fast k5_U (18us) and pre-dup'd k6.
//  K0 : A_qk[512][64] = W_in @ blockdiag(W_q|W_k); c_qk
//  K1f: per 256-row chunk: logits; qsm; chunk k-stats; Spart
//  K2b: scale[b][ch][j]
//  K5 : U = ((S @ W_in_h + b_in_h) @ W_v) @ W_out_h  (parallel, MLP-8)
//  K6 : out = b_out + qsm @ U
#include <cuda_runtime.h>
#include <cstdint>

typedef unsigned long long ull;

#define Bb   8
#define Nn   16384
#define DIMM 512
#define Hh   8
#define DHh  64
#define Rr   4
#define Jj   32
#define SCH  64          // chunks per batch (256 rows each)

// ---------------- scratch ----------------
__device__ __align__(16) float g_Aqk[DIMM * 64];
__device__ __align__(16) float g_cqk[64];
__device__ __align__(16) float g_qsm[(size_t)Bb * Nn * Jj];     // [b][n][32]
__device__ __align__(16) float g_mloc[(size_t)Bb * SCH * Jj];
__device__ __align__(16) float g_zloc[(size_t)Bb * SCH * Jj];
__device__ __align__(16) float g_scale[(size_t)Bb * SCH * Jj];
__device__ __align__(16) float g_Spart[(size_t)Bb * SCH * Jj * DIMM];
__device__ __align__(16) float g_U[(size_t)Bb * Jj * DIMM];

// ---------------- helpers ----------------
__device__ __forceinline__ ull ffma2(ull a, ull b, ull c) {
    ull d;
    asm("fma.rn.f32x2 %0, %1, %2, %3;" : "=l"(d) : "l"(a), "l"(b), "l"(c));
    return d;
}
__device__ __forceinline__ ull dup2(float f) {
    unsigned u = __float_as_uint(f);
    ull d;
    asm("mov.b64 %0, {%1, %1};" : "=l"(d) : "r"(u));
    return d;
}
__device__ __forceinline__ float ulo(ull u) { return __uint_as_float((unsigned)u); }
__device__ __forceinline__ float uhi(ull u) { return __uint_as_float((unsigned)(u >> 32)); }

__device__ __forceinline__ void cpa16(uint32_t smem_dst, const void* gsrc) {
    asm volatile("cp.async.cg.shared.global [%0], [%1], 16;" :: "r"(smem_dst), "l"(gsrc));
}
__device__ __forceinline__ void cpa_commit() { asm volatile("cp.async.commit_group;"); }
__device__ __forceinline__ void cpa_wait1() { asm volatile("cp.async.wait_group 1;"); }
__device__ __forceinline__ void cpa_wait0() { asm volatile("cp.async.wait_group 0;"); }

// ---------------- K0 ----------------
__global__ void k0_prep(const float* __restrict__ W_in, const float* __restrict__ b_in,
                        const float* __restrict__ W_q, const float* __restrict__ W_k) {
    int j = blockIdx.x;                      // 0..63 (q: 0..31, k: 32..63)
    const float* Wqk = (j < 32) ? W_q : W_k;
    int jj = j & 31, h = jj >> 2, r = jj & 3;
    int D = threadIdx.x;                     // 512 threads
    const float* wrow = W_in + (size_t)D * DIMM + h * DHh;
    float s = 0.f;
    #pragma unroll 8
    for (int d = 0; d < DHh; d++) s += wrow[d] * Wqk[d * Rr + r];
    g_Aqk[(size_t)D * 64 + j] = s;
    if (D == 0) {
        float c = 0.f;
        for (int d = 0; d < DHh; d++) c += b_in[h * DHh + d] * Wqk[d * Rr + r];
        g_cqk[j] = c;
    }
}

// ---------------- K1f: fused logits + q-softmax + chunk S-partials (r4) ----------
// smem layout (dynamic, 100608 B):
//  phase A : xs [0,73728) = 2*256*36 f32 ; ws [73728,90112) = 2*32*64 f32
//  epilogue: wsm [0,32768) = 256*32 f32 ; stag [32768,98560) = 64*257 f32 ;
//            red [98560,100608) = 512 f32  (mred[8][32], zred[8][32])
//  phase B : wsm persists ; xs2 [32768,65536) = 2*8*512 f32
#define K1F_SMEM 100608

__global__ void __launch_bounds__(256, 2) k1f(const float* __restrict__ x) {
    extern __shared__ char sm[];
    float* xs = (float*)sm;
    float* ws = (float*)(sm + 73728);
    int tid = threadIdx.x;
    int bi  = blockIdx.x;                  // 0..511
    size_t row0 = (size_t)bi * 256;
    int b  = (int)(row0 >> 14);
    int n0 = (int)(row0 & (Nn - 1));
    const float* xb = x + row0 * DIMM;
    uint32_t xs_s = (uint32_t)__cvta_generic_to_shared(xs);
    uint32_t ws_s = (uint32_t)__cvta_generic_to_shared(ws);

    // ================= Phase A: logits =================
    int cg = tid & 7, rg = tid >> 3;
    int c0 = cg * 8;

    ull acc[8][4];
    #pragma unroll
    for (int i = 0; i < 8; i++)
        #pragma unroll
        for (int m = 0; m < 4; m++) acc[i][m] = 0ull;

    #define K1_ISSUE(s) do {                                                     \
        int buf_ = (s) & 1;                                                      \
        const float* src_ = xb + (size_t)tid * DIMM + (s) * 32;                  \
        uint32_t dst_ = xs_s + (uint32_t)(buf_ * 36864 + tid * 144);             \
        _Pragma("unroll")                                                        \
        for (int i_ = 0; i_ < 8; i_++) cpa16(dst_ + i_ * 16, src_ + i_ * 4);     \
        const float* wsrc_ = g_Aqk + (s) * 32 * 64;                              \
        uint32_t wdst_ = ws_s + (uint32_t)(buf_ * 8192);                         \
        _Pragma("unroll")                                                        \
        for (int i_ = 0; i_ < 2; i_++) {                                         \
            int c_ = tid * 2 + i_;                                               \
            cpa16(wdst_ + c_ * 16, wsrc_ + c_ * 4);                              \
        }                                                                        \
    } while (0)

    K1_ISSUE(0); cpa_commit();
    for (int s = 0; s < 16; s++) {
        if (s < 15) { K1_ISSUE(s + 1); cpa_commit(); cpa_wait1(); }
        else        { cpa_wait0(); }
        __syncthreads();
        const float* xbuf = xs + (s & 1) * 9216;
        const float* wbuf = ws + (s & 1) * 2048;
        #pragma unroll 8
        for (int kk = 0; kk < 32; kk++) {
            ull xd[8];
            #pragma unroll
            for (int i = 0; i < 8; i++) xd[i] = dup2(xbuf[(rg + 32 * i) * 36 + kk]);
            ulonglong2 w01 = *(const ulonglong2*)(wbuf + kk * 64 + c0);
            ulonglong2 w23 = *(const ulonglong2*)(wbuf + kk * 64 + c0 + 4);
            #pragma unroll
            for (int i = 0; i < 8; i++) {
                acc[i][0] = ffma2(xd[i], w01.x, acc[i][0]);
                acc[i][1] = ffma2(xd[i], w01.y, acc[i][1]);
                acc[i][2] = ffma2(xd[i], w23.x, acc[i][2]);
                acc[i][3] = ffma2(xd[i], w23.y, acc[i][3]);
            }
        }
        __syncthreads();
    }

    // ================= Epilogue: stag + q-softmax + k chunk-stats =================
    float* wsm  = (float*)sm;                  // [256 n][32 j]
    float* stag = (float*)(sm + 32768);        // [64 c][257]
    float* mred = (float*)(sm + 98560);        // [8][32]
    float* zred = mred + 256;

    {
        float cq[8];
        #pragma unroll
        for (int j = 0; j < 8; j++) cq[j] = g_cqk[c0 + j];
        #pragma unroll
        for (int i = 0; i < 8; i++) {
            int r = rg + 32 * i;
            #pragma unroll
            for (int m = 0; m < 4; m++) {
                stag[(c0 + 2 * m) * 257 + r]     = ulo(acc[i][m]) + cq[2 * m];
                stag[(c0 + 2 * m + 1) * 257 + r] = uhi(acc[i][m]) + cq[2 * m + 1];
            }
        }
    }
    __syncthreads();

    // q softmax: thread = one n
    {
        float4 qs[8];
        #pragma unroll
        for (int h = 0; h < 8; h++) {
            float v0 = stag[(4 * h + 0) * 257 + tid];
            float v1 = stag[(4 * h + 1) * 257 + tid];
            float v2 = stag[(4 * h + 2) * 257 + tid];
            float v3 = stag[(4 * h + 3) * 257 + tid];
            float mx = fmaxf(fmaxf(v0, v1), fmaxf(v2, v3));
            float e0 = __expf(v0 - mx), e1 = __expf(v1 - mx);
            float e2 = __expf(v2 - mx), e3 = __expf(v3 - mx);
            float inv = 1.0f / (e0 + e1 + e2 + e3);
            qs[h] = make_float4(e0 * inv, e1 * inv, e2 * inv, e3 * inv);
        }
        float* dst = g_qsm + ((size_t)b * Nn + n0 + tid) * Jj;
        #pragma unroll
        for (int h = 0; h < 8; h++) *(float4*)(dst + h * 4) = qs[h];
    }

    // k chunk-local stats + weights: thread = (j = tid&31, grp = tid>>5)
    {
        int j = tid & 31, grp = tid >> 5;
        const float* kl = stag + (32 + j) * 257 + grp * 32;
        float mloc = -3.4e38f;
        #pragma unroll 8
        for (int nn = 0; nn < 32; nn++) mloc = fmaxf(mloc, kl[nn]);
        mred[grp * 32 + j] = mloc;
        __syncthreads();
        float Mj = -3.4e38f;
        #pragma unroll
        for (int g = 0; g < 8; g++) Mj = fmaxf(Mj, mred[g * 32 + j]);
        float zloc = 0.f;
        #pragma unroll 8
        for (int nn = 0; nn < 32; nn++) {
            float w = __expf(kl[nn] - Mj);
            zloc += w;
            wsm[(grp * 32 + nn) * 32 + j] = w;
        }
        zred[grp * 32 + j] = zloc;
        __syncthreads();
        if (tid < 32) {
            float z = 0.f;
            #pragma unroll
            for (int g = 0; g < 8; g++) z += zred[g * 32 + tid];
            g_mloc[(size_t)bi * Jj + tid] = Mj;
            g_zloc[(size_t)bi * Jj + tid] = z;
        }
    }
    __syncthreads();   // wsm complete; stag dead -> xs2 region reusable

    // ================= Phase B: S partials =================
    float* xs2 = (float*)(sm + 32768);         // 2 * 8*512 f32
    uint32_t xs2_s = (uint32_t)__cvta_generic_to_shared(xs2);
    int jg = tid >> 6, dg = tid & 63;
    int j0 = jg * 8;
    int d0 = dg * 4;

    #define K3_ISSUE(s) do {                                                     \
        int buf_ = (s) & 1;                                                      \
        const float* src_ = xb + (size_t)(s) * 8 * DIMM;                         \
        uint32_t dst_ = xs2_s + (uint32_t)(buf_ * 16384);                        \
        _Pragma("unroll")                                                        \
        for (int t_ = 0; t_ < 4; t_++) {                                         \
            int c_ = tid + t_ * 256;                                             \
            cpa16(dst_ + c_ * 16, src_ + c_ * 4);                                \
        }                                                                        \
    } while (0)

    ull sacc[8][4];
    #pragma unroll
    for (int i = 0; i < 8; i++)
        #pragma unroll
        for (int m = 0; m < 4; m++) sacc[i][m] = 0ull;

    K3_ISSUE(0); cpa_commit();
    for (int s = 0; s < 32; s++) {
        if (s < 31) { K3_ISSUE(s + 1); cpa_commit(); cpa_wait1(); }
        else        { cpa_wait0(); }
        __syncthreads();
        const float* xbuf = xs2 + (s & 1) * 4096;
        const float* wrow = wsm + s * 8 * 32;
        #pragma unroll
        for (int nn = 0; nn < 8; nn++) {
            ull wd[8];
            #pragma unroll
            for (int i = 0; i < 8; i++) wd[i] = dup2(wrow[nn * 32 + j0 + i]);
            ulonglong2 x01 = *(const ulonglong2*)(xbuf + nn * 512 + d0);
            ulonglong2 x23 = *(const ulonglong2*)(xbuf + nn * 512 + 256 + d0);
            #pragma unroll
            for (int i = 0; i < 8; i++) {
                sacc[i][0] = ffma2(wd[i], x01.x, sacc[i][0]);
                sacc[i][1] = ffma2(wd[i], x01.y, sacc[i][1]);
                sacc[i][2] = ffma2(wd[i], x23.x, sacc[i][2]);
                sacc[i][3] = ffma2(wd[i], x23.y, sacc[i][3]);
            }
        }
        __syncthreads();
    }
    float* dst = g_Spart + ((size_t)bi * Jj) * DIMM;
    #pragma unroll
    for (int i = 0; i < 8; i++) {
        int j = j0 + i;
        *(float4*)(dst + (size_t)j * DIMM + d0) =
            make_float4(ulo(sacc[i][0]), uhi(sacc[i][0]), ulo(sacc[i][1]), uhi(sacc[i][1]));
        *(float4*)(dst + (size_t)j * DIMM + 256 + d0) =
            make_float4(ulo(sacc[i][2]), uhi(sacc[i][2]), ulo(sacc[i][3]), uhi(sacc[i][3]));
    }
}

// ---------------- K2b: combine chunk stats -> per-chunk scale ----------------
__global__ void k2b_scale() {
    int bj = blockIdx.x;              // 0..255
    int b = bj >> 5, j = bj & 31;
    __shared__ float smv[64], szv[64];
    int ch = threadIdx.x;             // 64 threads
    float m = g_mloc[(size_t)(b * SCH + ch) * Jj + j];
    float z = g_zloc[(size_t)(b * SCH + ch) * Jj + j];
    smv[ch] = m;
    __syncthreads();
    float M = -3.4e38f;
    #pragma unroll
    for (int c = 0; c < 64; c++) M = fmaxf(M, smv[c]);
    szv[ch] = z * __expf(m - M);
    __syncthreads();
    float Z = 0.f;
    #pragma unroll
    for (int c = 0; c < 64; c++) Z += szv[c];
    g_scale[(size_t)(b * SCH + ch) * Jj + j] = __expf(m - M) / Z;
}

// ---------------- K5 (r5: parallel T-stage, MLP-8 reduction) ----------------
__global__ void __launch_bounds__(512) k5_U(
        const float* __restrict__ W_in, const float* __restrict__ b_in,
        const float* __restrict__ W_v, const float* __restrict__ W_out) {
    int bj = blockIdx.x;
    int b = bj >> 5, j = bj & 31, h = j >> 2;
    __shared__ float scl[SCH];
    __shared__ float Srow[DIMM];
    __shared__ float Tp[DIMM];
    __shared__ float T[DHh];
    __shared__ float kv[DHh];
    int tid = threadIdx.x;   // 512
    if (tid < SCH) scl[tid] = g_scale[(size_t)(b * SCH + tid) * Jj + j];
    __syncthreads();
    {
        const float* base = g_Spart + (((size_t)b * SCH) * Jj + j) * DIMM + tid;
        float a[8];
        #pragma unroll
        for (int u = 0; u < 8; u++) a[u] = 0.f;
        #pragma unroll
        for (int c8 = 0; c8 < 8; c8++)
            #pragma unroll
            for (int u = 0; u < 8; u++) {
                int ch = c8 * 8 + u;
                a[u] += base[(size_t)ch * (Jj * DIMM)] * scl[ch];
            }
        Srow[tid] = ((a[0] + a[1]) + (a[2] + a[3])) + ((a[4] + a[5]) + (a[6] + a[7]));
    }
    __syncthreads();
    {   // T[d] = b_in + sum_D Srow[D] * W_in[D][h*64+d], parallel over (d, Dpart)
        int d = tid & 63, part = tid >> 6;    // 8 parts of 64 D
        float s = 0.f;
        const float* wp = W_in + (size_t)(part * 64) * DIMM + h * DHh + d;
        #pragma unroll 8
        for (int Dp = 0; Dp < 64; Dp++) s += Srow[part * 64 + Dp] * wp[(size_t)Dp * DIMM];
        Tp[part * 64 + d] = s;
    }
    __syncthreads();
    if (tid < DHh) {
        float t = b_in[h * DHh + tid];
        #pragma unroll
        for (int p = 0; p < 8; p++) t += Tp[p * 64 + tid];
        T[tid] = t;
    }
    __syncthreads();
    if (tid < DHh) {
        float s = 0.f;
        for (int d = 0; d < DHh; d++) s += T[d] * W_v[d * DHh + tid];
        kv[tid] = s;
    }
    __syncthreads();
    {
        float u = 0.f;
        for (int c = 0; c < DHh; c++) u += kv[c] * W_out[(size_t)(h * DHh + c) * DIMM + tid];
        g_U[(size_t)bj * DIMM + tid] = u;
    }
}

// ---------------- K6: out = b_out + qsm @ U  (64n x 256e per block) ----------------
__global__ void __launch_bounds__(256) k6_out(const float* __restrict__ b_out,
                                              float* __restrict__ out) {
    __shared__ ull   qsd[64 * 33];     // [n][j] pre-dup'd
    __shared__ float us[Jj * 256];     // [j][e]
    __shared__ float bo[256];
    int tid = threadIdx.x;
    int b = blockIdx.z;
    int n0 = blockIdx.y * 64;
    int e0 = blockIdx.x * 256;

    #pragma unroll
    for (int t = 0; t < 2; t++) {
        int idx = tid + t * 256;       // 512 float4
        int row = idx >> 3, q = idx & 7;
        float4 v = *(const float4*)(g_qsm + ((size_t)b * Nn + n0 + row) * Jj + q * 4);
        ull* dq = qsd + row * 33 + q * 4;
        dq[0] = dup2(v.x); dq[1] = dup2(v.y); dq[2] = dup2(v.z); dq[3] = dup2(v.w);
    }
    #pragma unroll
    for (int t = 0; t < 8; t++) {
        int idx = tid + t * 256;       // 2048 float4
        int j = idx >> 6, q = idx & 63;
        ((float4*)us)[j * 64 + q] =
            *(const float4*)(g_U + ((size_t)(b * Jj + j)) * DIMM + e0 + q * 4);
    }
    if (tid < 64) ((float4*)bo)[tid] = *(const float4*)(b_out + e0 + tid * 4);
    __syncthreads();

    int tx = tid & 15, ty = tid >> 4;
    int nl = ty * 4, eb = tx * 4;
    ull acc[4][8];
    #pragma unroll
    for (int i = 0; i < 4; i++)
        #pragma unroll
        for (int m = 0; m < 8; m++) acc[i][m] = 0ull;

    #pragma unroll 4
    for (int j = 0; j < Jj; j++) {
        ull a[4];
        #pragma unroll
        for (int i = 0; i < 4; i++) a[i] = qsd[(nl + i) * 33 + j];
        const float* ur = us + j * 256;
        ulonglong2 u0 = *(const ulonglong2*)(ur + eb);
        ulonglong2 u1 = *(const ulonglong2*)(ur + 64 + eb);
        ulonglong2 u2 = *(const ulonglong2*)(ur + 128 + eb);
        ulonglong2 u3 = *(const ulonglong2*)(ur + 192 + eb);
        #pragma unroll
        for (int i = 0; i < 4; i++) {
            acc[i][0] = ffma2(a[i], u0.x, acc[i][0]);
            acc[i][1] = ffma2(a[i], u0.y, acc[i][1]);
            acc[i][2] = ffma2(a[i], u1.x, acc[i][2]);
            acc[i][3] = ffma2(a[i], u1.y, acc[i][3]);
            acc[i][4] = ffma2(a[i], u2.x, acc[i][4]);
            acc[i][5] = ffma2(a[i], u2.y, acc[i][5]);
            acc[i][6] = ffma2(a[i], u3.x, acc[i][6]);
            acc[i][7] = ffma2(a[i], u3.y, acc[i][7]);
        }
    }

    #pragma unroll
    for (int i = 0; i < 4; i++) {
        float* row = out + ((size_t)b * Nn + n0 + nl + i) * DIMM + e0;
        #pragma unroll
        for (int seg = 0; seg < 4; seg++) {
            float4 v;
            v.x = ulo(acc[i][2 * seg])     + bo[seg * 64 + eb + 0];
            v.y = uhi(acc[i][2 * seg])     + bo[seg * 64 + eb + 1];
            v.z = ulo(acc[i][2 * seg + 1]) + bo[seg * 64 + eb + 2];
            v.w = uhi(acc[i][2 * seg + 1]) + bo[seg * 64 + eb + 3];
            *(float4*)(row + seg * 64 + eb) = v;
        }
    }
}

// ---------------- launch ----------------
extern "C" void kernel_launch(void* const* d_in, const int* in_sizes, int n_in,
                              void* d_out, int out_size) {
    const float* x     = (const float*)d_in[0];
    const float* W_in  = (const float*)d_in[1];
    const float* b_in  = (const float*)d_in[2];
    const float* W_q   = (const float*)d_in[3];
    const float* W_k   = (const float*)d_in[4];
    const float* W_v   = (const float*)d_in[5];
    const float* W_out = (const float*)d_in[6];
    const float* b_out = (const float*)d_in[7];
    float* out = (float*)d_out;

    cudaFuncSetAttribute(k1f, cudaFuncAttributeMaxDynamicSharedMemorySize, K1F_SMEM);

    k0_prep<<<64, 512>>>(W_in, b_in, W_q, W_k);
    k1f<<<Bb * SCH, 256, K1F_SMEM>>>(x);
    k2b_scale<<<Bb * Jj, 64>>>();
    k5_U<<<Bb * Jj, 512>>>(W_in, b_in, W_v, W_out);
    dim3 g6(DIMM / 256, Nn / 64, Bb);
    k6_out<<<g6, 256>>>(b_out, out);
}